// round 3
// baseline (speedup 1.0000x reference)
#include <cuda_runtime.h>
#include <math.h>

// Problem constants
#define BB 128    // batch
#define TT 80     // caption length
#define TS 79     // time steps (T-1)
#define VV 10000  // vocab
#define EE 512    // embed dim
#define II 512    // factor dim
#define HH 512    // hidden dim
#define SS 300    // semantics dim
#define CC 2048   // cnn feature dim
#define GG 4      // gates

// ---------------- scratch (single __device__ global, ~215MB) ----------------
constexpr long GBI      = (long)GG * BB * II;          // 262144
constexpr long OFF_BX   = 0;
constexpr long OFF_BH   = OFF_BX + GBI;
constexpr long OFF_BV   = OFF_BH + GBI;
constexpr long OFF_AV   = OFF_BV + GBI;                // holds av*bv
constexpr long OFF_CV   = OFF_AV + GBI;
constexpr long EMBS_SZ  = (long)TS * BB * EE;          // 5,177,344
constexpr long OFF_EMBS = OFF_CV + GBI;
constexpr long AXB_SZ   = (long)GG * TS * BB * II;     // 20,709,376
constexpr long OFF_AXB  = OFF_EMBS + EMBS_SZ;
constexpr long OFF_PRE  = OFF_AXB + AXB_SZ;            // cx + cv + bias, all t
constexpr long OFF_AHB  = OFF_PRE + AXB_SZ;
constexpr long OFF_GATES= OFF_AHB + GBI;
constexpr long OFF_H    = OFF_GATES + GBI;
constexpr long OFF_C    = OFF_H + (long)BB * HH;
constexpr long OFF_HALL = OFF_C + (long)BB * HH;
constexpr long SC_TOTAL = OFF_HALL + (long)TS * BB * HH;

__device__ float g_scratch[SC_TOTAL];

// ---------------- packed f32x2 FMA (SASS FFMA2, Blackwell-only) ----------------
typedef unsigned long long u64;

__device__ __forceinline__ u64 ffma2(u64 a, u64 b, u64 c) {
    u64 d;
    asm("fma.rn.f32x2 %0, %1, %2, %3;" : "=l"(d) : "l"(a), "l"(b), "l"(c));
    return d;
}

__device__ __forceinline__ float hadd2(u64 v) {
    float lo = __uint_as_float((unsigned)(v & 0xFFFFFFFFull));
    float hi = __uint_as_float((unsigned)(v >> 32));
    return lo + hi;
}

// ---------------- tiled SGEMM, K-vectorized FFMA2, conflict-free LDS ----------------
// out[g,m,n] = (sum_k A[g(opt),m,k] * W[g,k,n]) * Mul[g,(m%B),n]? + Add? + Bias[g,n]?
// outMode 0: C[g*M*N + m*N + n]
// outMode 1: logits remap, m=(t*B+b): C[(b*TS + t)*N + n]
//
// Interleaved thread->output mapping: m = m0 + ty + i*TY, n = n0 + tx + j*TX.
// Shared tiles K-contiguous (As[BM][BKP], Ws[BN][BKP], BKP/2 = 9 u64, odd) so
// per-lane LDS.64 stride is 9 u64 -> all 16 lanes/phase hit distinct bank pairs.
template<int BM, int BN, int BK, int TM, int TN, int TX, int TY>
__global__ void __launch_bounds__(TX * TY)
sgemm_k(const float* __restrict__ A, const float* __restrict__ W,
        float* __restrict__ C,
        const float* __restrict__ Mul,
        const float* __restrict__ Add,
        const float* __restrict__ Bias,
        int M, int N, int K,
        long aStrideG, long addStrideG, int addModB, int outMode)
{
    constexpr int BKP = BK + 2;           // 18 floats/row -> 9 u64 (odd stride)
    static_assert(BK % 4 == 0 && BKP % 2 == 0, "");
    __shared__ __align__(16) float As[BM * BKP];
    __shared__ __align__(16) float Ws[BN * BKP];

    const int g  = blockIdx.z;
    const int m0 = blockIdx.y * BM;
    const int n0 = blockIdx.x * BN;
    const float* Ag = A + (long)g * aStrideG;
    const float* Wg = W + (long)g * (long)K * N;
    const int tx = threadIdx.x, ty = threadIdx.y;
    const int tid = ty * TX + tx;
    const int NT  = TX * TY;

    u64 acc[TM][TN];
#pragma unroll
    for (int i = 0; i < TM; i++)
#pragma unroll
        for (int j = 0; j < TN; j++) acc[i][j] = 0ull;

    const u64* As64 = reinterpret_cast<const u64*>(As);
    const u64* Ws64 = reinterpret_cast<const u64*>(Ws);

    for (int k0 = 0; k0 < K; k0 += BK) {
        // A tile: one float4 per thread (BM*BK/4 == NT for 64x16/256)
        for (int idx = tid; idx < BM * (BK / 4); idx += NT) {
            int mm = idx / (BK / 4), kq = idx % (BK / 4);
            int m = m0 + mm, k = k0 + kq * 4;
            float4 v;
            if (m < M && k + 3 < K) {
                v = *reinterpret_cast<const float4*>(Ag + (long)m * K + k);
            } else {
                v.x = (m < M && k + 0 < K) ? Ag[(long)m * K + k + 0] : 0.f;
                v.y = (m < M && k + 1 < K) ? Ag[(long)m * K + k + 1] : 0.f;
                v.z = (m < M && k + 2 < K) ? Ag[(long)m * K + k + 2] : 0.f;
                v.w = (m < M && k + 3 < K) ? Ag[(long)m * K + k + 3] : 0.f;
            }
            float* dst = As + mm * BKP + kq * 4;
            dst[0] = v.x; dst[1] = v.y; dst[2] = v.z; dst[3] = v.w;
        }
        // W tile: one float4 per thread along n, transposed into Ws[n][k]
        for (int idx = tid; idx < BK * (BN / 4); idx += NT) {
            int kk = idx / (BN / 4), nq = idx % (BN / 4);
            int k = k0 + kk, n = n0 + nq * 4;
            float4 v;
            if (k < K && n + 3 < N) {
                v = *reinterpret_cast<const float4*>(Wg + (long)k * N + n);
            } else {
                v.x = (k < K && n + 0 < N) ? Wg[(long)k * N + n + 0] : 0.f;
                v.y = (k < K && n + 1 < N) ? Wg[(long)k * N + n + 1] : 0.f;
                v.z = (k < K && n + 2 < N) ? Wg[(long)k * N + n + 2] : 0.f;
                v.w = (k < K && n + 3 < N) ? Wg[(long)k * N + n + 3] : 0.f;
            }
            Ws[(nq * 4 + 0) * BKP + kk] = v.x;
            Ws[(nq * 4 + 1) * BKP + kk] = v.y;
            Ws[(nq * 4 + 2) * BKP + kk] = v.z;
            Ws[(nq * 4 + 3) * BKP + kk] = v.w;
        }
        __syncthreads();

#pragma unroll
        for (int kp = 0; kp < BK / 2; kp++) {
            u64 a2[TM], b2[TN];
#pragma unroll
            for (int i = 0; i < TM; i++)
                a2[i] = As64[(ty + i * TY) * (BKP / 2) + kp];   // broadcast over tx
#pragma unroll
            for (int j = 0; j < TN; j++)
                b2[j] = Ws64[(tx + j * TX) * (BKP / 2) + kp];   // stride 9 u64: conflict-free
#pragma unroll
            for (int i = 0; i < TM; i++)
#pragma unroll
                for (int j = 0; j < TN; j++)
                    acc[i][j] = ffma2(a2[i], b2[j], acc[i][j]);
        }
        __syncthreads();
    }

#pragma unroll
    for (int i = 0; i < TM; i++) {
        int m = m0 + ty + i * TY;
        if (m >= M) continue;
        int bb = m % BB;
#pragma unroll
        for (int j = 0; j < TN; j++) {
            int n = n0 + tx + j * TX;
            if (n >= N) continue;
            float v = hadd2(acc[i][j]);
            if (Mul)  v *= Mul[(long)g * BB * N + (long)bb * N + n];
            if (Add)  v += Add[(long)g * addStrideG + (long)(addModB ? bb : m) * N + n];
            if (Bias) v += Bias[(long)g * N + n];
            long o = (outMode == 0) ? ((long)g * M * N + (long)m * N + n)
                                    : (((long)bb * TS + (m / BB)) * (long)N + n);
            C[o] = v;
        }
    }
}

// One config for everything: 64x64 tile, BK=16, 4x4 per thread, 256 threads.
static void launch_gemm(const float* A, const float* W, float* C,
                        const float* Mul, const float* Add, const float* Bias,
                        int M, int N, int K, int G,
                        long aStrideG, long addStrideG, int addModB, int outMode)
{
    dim3 grid((N + 63) / 64, (M + 63) / 64, G), block(16, 16);
    sgemm_k<64, 64, 16, 4, 4, 16, 16><<<grid, block>>>(
        A, W, C, Mul, Add, Bias, M, N, K, aStrideG, addStrideG, addModB, outMode);
}

// ---------------- small helper kernels ----------------
__global__ void k_zero2(float* a, float* b, int n)
{
    int i = blockIdx.x * blockDim.x + threadIdx.x;
    if (i < n) { a[i] = 0.f; b[i] = 0.f; }
}

// embs stored time-major: embs[(t*B + b)*E + e] = table[cap[b*T + t]*E + e]
__global__ void k_embed(const int* __restrict__ cap, const float* __restrict__ table,
                        float* __restrict__ embs)
{
    int tb = blockIdx.x;              // 0 .. TS*B-1
    int t = tb / BB, b = tb % BB;
    int tok = cap[b * TT + t];
    const float4* src = reinterpret_cast<const float4*>(table + (long)tok * EE);
    float4* dst = reinterpret_cast<float4*>(embs + (long)tb * EE);
    dst[threadIdx.x] = src[threadIdx.x];   // 128 threads x float4 = 512 floats
}

__global__ void k_update(const float* __restrict__ gates, float* __restrict__ c,
                         float* __restrict__ h, float* __restrict__ hall_t)
{
    int idx = blockIdx.x * blockDim.x + threadIdx.x;
    if (idx >= BB * HH) return;
    float gi = gates[0 * BB * HH + idx];
    float gf = gates[1 * BB * HH + idx];
    float go = gates[2 * BB * HH + idx];
    float gg = gates[3 * BB * HH + idx];
    float i_g = 1.f / (1.f + expf(-gi));
    float f_g = 1.f / (1.f + expf(-gf));
    float o_g = 1.f / (1.f + expf(-go));
    float g_g = tanhf(gg);
    float cc = f_g * c[idx] + i_g * g_g;
    float hh = o_g * tanhf(cc);
    c[idx] = cc;
    h[idx] = hh;
    hall_t[idx] = hh;
}

// ---------------- launch ----------------
extern "C" void kernel_launch(void* const* d_in, const int* in_sizes, int n_in,
                              void* d_out, int out_size)
{
    const int*   cap   = (const int*)  d_in[0];
    const float* cnn   = (const float*)d_in[1];
    const float* sem   = (const float*)d_in[2];
    const float* Wa_x  = (const float*)d_in[3];
    const float* Wb_x  = (const float*)d_in[4];
    const float* Wc_x  = (const float*)d_in[5];
    const float* Wa_h  = (const float*)d_in[6];
    const float* Wb_h  = (const float*)d_in[7];
    const float* Wc_h  = (const float*)d_in[8];
    const float* Wa_v  = (const float*)d_in[9];
    const float* Wb_v  = (const float*)d_in[10];
    const float* Wc_v  = (const float*)d_in[11];
    const float* bias  = (const float*)d_in[12];
    const float* table = (const float*)d_in[13];
    const float* Wout  = (const float*)d_in[14];
    const float* bout  = (const float*)d_in[15];
    float* out = (float*)d_out;

    float* S = nullptr;
    cudaGetSymbolAddress((void**)&S, g_scratch);
    float* bx    = S + OFF_BX;
    float* bh    = S + OFF_BH;
    float* bv    = S + OFF_BV;
    float* avbv  = S + OFF_AV;
    float* cv    = S + OFF_CV;
    float* embs  = S + OFF_EMBS;
    float* axb   = S + OFF_AXB;
    float* pre   = S + OFF_PRE;
    float* ahb   = S + OFF_AHB;
    float* gates = S + OFF_GATES;
    float* h     = S + OFF_H;
    float* c     = S + OFF_C;
    float* hall  = S + OFF_HALL;

    // reset recurrent state (deterministic per call)
    k_zero2<<<(BB * HH + 255) / 256, 256>>>(h, c, BB * HH);

    // embedding gather (time-major)
    k_embed<<<TS * BB, 128>>>(cap, table, embs);

    // semantics projections: bx/bh/bv[g,b,i] = sem @ Wb_*
    launch_gemm(sem, Wb_x, bx, nullptr, nullptr, nullptr, BB, II, SS, GG, 0, 0, 0, 0);
    launch_gemm(sem, Wb_h, bh, nullptr, nullptr, nullptr, BB, II, SS, GG, 0, 0, 0, 0);
    launch_gemm(sem, Wb_v, bv, nullptr, nullptr, nullptr, BB, II, SS, GG, 0, 0, 0, 0);

    // av*bv fused: (cnn @ Wa_v) * bv
    launch_gemm(cnn, Wa_v, avbv, bv, nullptr, nullptr, BB, II, CC, GG, 0, 0, 0, 0);
    // cv[g,b,h] = (av*bv) @ Wc_v
    launch_gemm(avbv, Wc_v, cv, nullptr, nullptr, nullptr, BB, HH, II, GG,
                (long)BB * II, 0, 0, 0);

    // All-timestep input path: axb[g,(t,b),i] = (embs @ Wa_x) * bx
    launch_gemm(embs, Wa_x, axb, bx, nullptr, nullptr, TS * BB, II, EE, GG, 0, 0, 0, 0);
    // pre[g,(t,b),h] = axb @ Wc_x + cv + bias    (full pre-gate, time-invariant parts folded)
    launch_gemm(axb, Wc_x, pre, nullptr, cv, bias, TS * BB, HH, II, GG,
                (long)TS * BB * II, (long)BB * HH, 1, 0);

    // Sequential recurrence: only the h-path is serial
    for (int t = 0; t < TS; t++) {
        // ahb[g,b,i] = (h @ Wa_h) * bh
        launch_gemm(h, Wa_h, ahb, bh, nullptr, nullptr, BB, II, HH, GG, 0, 0, 0, 0);
        // gates[g,b,h] = ahb @ Wc_h + pre[g,t,b,h]
        launch_gemm(ahb, Wc_h, gates, nullptr, pre + (long)t * BB * HH, nullptr,
                    BB, HH, II, GG, (long)BB * II, (long)TS * BB * HH, 0, 0);
        // LSTM cell update; store h into hall[t]
        k_update<<<(BB * HH + 255) / 256, 256>>>(gates, c, h, hall + (long)t * BB * HH);
    }

    // Logits for all timesteps: out[b,t,v] = hall[(t,b),:] @ Wout + bout
    launch_gemm(hall, Wout, out, nullptr, nullptr, bout, TS * BB, VV, HH, 1, 0, 0, 0, 1);
}

// round 4
// speedup vs baseline: 1.1652x; 1.1652x over previous
#include <cuda_runtime.h>
#include <math.h>

// Problem constants
#define BB 128    // batch
#define TT 80     // caption length
#define TS 79     // time steps (T-1)
#define VV 10000  // vocab
#define EE 512    // embed dim
#define II 512    // factor dim
#define HH 512    // hidden dim
#define SS 300    // semantics dim
#define CC 2048   // cnn feature dim
#define GG 4      // gates

// ---------------- scratch (single __device__ global) ----------------
constexpr long GBI      = (long)GG * BB * II;          // 262144
constexpr long OFF_BX   = 0;
constexpr long OFF_BH   = OFF_BX + GBI;
constexpr long OFF_BV   = OFF_BH + GBI;
constexpr long OFF_AV   = OFF_BV + GBI;                // holds av*bv
constexpr long OFF_CV   = OFF_AV + GBI;
constexpr long EMBS_SZ  = (long)TS * BB * EE;
constexpr long OFF_EMBS = OFF_CV + GBI;
constexpr long AXB_SZ   = (long)GG * TS * BB * II;
constexpr long OFF_AXB  = OFF_EMBS + EMBS_SZ;
constexpr long OFF_PRE  = OFF_AXB + AXB_SZ;            // cx + cv + bias, all t
constexpr long OFF_AHB  = OFF_PRE + AXB_SZ;
constexpr long OFF_GATES= OFF_AHB + GBI;
constexpr long OFF_H    = OFF_GATES + GBI;
constexpr long OFF_C    = OFF_H + (long)BB * HH;
constexpr long OFF_HALL = OFF_C + (long)BB * HH;
constexpr long SC_TOTAL = OFF_HALL + (long)TS * BB * HH;

__device__ float g_scratch[SC_TOTAL];

// ---------------- packed f32x2 ops (SASS FFMA2 etc., Blackwell) ----------------
typedef unsigned long long u64;

__device__ __forceinline__ u64 ffma2(u64 a, u64 b, u64 c) {
    u64 d;
    asm("fma.rn.f32x2 %0, %1, %2, %3;" : "=l"(d) : "l"(a), "l"(b), "l"(c));
    return d;
}
__device__ __forceinline__ u64 fadd2(u64 a, u64 b) {
    u64 d;
    asm("add.rn.f32x2 %0, %1, %2;" : "=l"(d) : "l"(a), "l"(b));
    return d;
}
__device__ __forceinline__ u64 fmul2(u64 a, u64 b) {
    u64 d;
    asm("mul.rn.f32x2 %0, %1, %2;" : "=l"(d) : "l"(a), "l"(b));
    return d;
}
__device__ __forceinline__ u64 pack2(float x) {
    u64 d; unsigned u = __float_as_uint(x);
    asm("mov.b64 %0, {%1, %1};" : "=l"(d) : "r"(u));
    return d;
}
__device__ __forceinline__ float hadd2(u64 v) {
    float lo = __uint_as_float((unsigned)(v & 0xFFFFFFFFull));
    float hi = __uint_as_float((unsigned)(v >> 32));
    return lo + hi;
}

// ================= rec_gemm: specialized B=128, N=512 GEMM =================
// out[g][b][n] = (sum_k A[g][b][k] * W[g][k][n]) (*Mul[g][b][n])? (+Add[g][b][n])?
// Weights streamed from L2 with coalesced LDG.128 (n-contiguous native layout),
// f32x2 accumulators vectorized over n. 128 blocks x 256 thr, 4-way in-block
// K-split (ty) with f32x2 smem reduction. Thread owns 4b x 8n.
// grid: (4 n-tiles of 128, 8 b-tiles of 16, G)
#define RK_MAXK 512
__global__ void __launch_bounds__(256)
rec_gemm(const float* __restrict__ A, const float* __restrict__ W,
         float* __restrict__ Out,
         const float* __restrict__ Mul, const float* __restrict__ Add,
         int K, long aStrideG, long outStrideG, long addStrideG)
{
    __shared__ __align__(16) char smem_raw[(RK_MAXK + 2) * 16 * 4]; // 32.9KB, reused
    float* hs  = (float*)smem_raw;
    u64* part  = (u64*)smem_raw;

    const int g  = blockIdx.z;
    const int n0 = blockIdx.x * 128;
    const int b0 = blockIdx.y * 16;
    const int tid = threadIdx.x;
    const int tx = tid & 15;          // n-group: n = n0 + tx*8 .. +7
    const int by = (tid >> 4) & 3;    // b-subgroup: b = b0 + by*4 + {0..3}
    const int ty = tid >> 6;          // k-chunk (4-way split)
    const int KP = K + 2;             // padded smem row stride (bank-safe)

    const float* Ag = A + (long)g * aStrideG + (long)b0 * K;
    const float* Wg = W + (long)g * K * 512;

    // stage A tile (16 x K) into smem, padded rows
    {
        const int kq4 = K >> 2;
        for (int idx = tid; idx < 16 * kq4; idx += 256) {
            int r = idx / kq4, kq = idx % kq4;
            float4 v = *reinterpret_cast<const float4*>(Ag + (long)r * K + kq * 4);
            float* d = hs + r * KP + kq * 4;
            d[0] = v.x; d[1] = v.y; d[2] = v.z; d[3] = v.w;
        }
    }
    __syncthreads();

    u64 acc[4][4];
#pragma unroll
    for (int bl = 0; bl < 4; bl++)
#pragma unroll
        for (int iw = 0; iw < 4; iw++) acc[bl][iw] = 0ull;

    const int kchunk = K >> 2;
    const int kstart = ty * kchunk;
    const float* wbase = Wg + n0 + tx * 8;
    const float* hb = hs + (by * 4) * KP;

#pragma unroll 4
    for (int kc = 0; kc < kchunk; kc++) {
        const int k = kstart + kc;
        const float* wp = wbase + (long)k * 512;
        ulonglong2 wl = *reinterpret_cast<const ulonglong2*>(wp);
        ulonglong2 wh = *reinterpret_cast<const ulonglong2*>(wp + 4);
        u64 w_[4] = { wl.x, wl.y, wh.x, wh.y };
        u64 a_[4];
#pragma unroll
        for (int bl = 0; bl < 4; bl++) a_[bl] = pack2(hb[bl * KP + k]);
#pragma unroll
        for (int bl = 0; bl < 4; bl++)
#pragma unroll
            for (int iw = 0; iw < 4; iw++)
                acc[bl][iw] = ffma2(a_[bl], w_[iw], acc[bl][iw]);
    }

    __syncthreads();   // done with hs; reuse buffer for partials
    {
        const int base = ((by * 16 + tx) * 4) * 4;   // + bl*4 + iw
#pragma unroll
        for (int bl = 0; bl < 4; bl++)
#pragma unroll
            for (int iw = 0; iw < 4; iw++)
                part[ty * 1024 + base + bl * 4 + iw] = acc[bl][iw];
    }
    __syncthreads();

    // reduce 4 k-chunks; thread handles 4 consecutive flat slots (= 4 n-pairs of one (b))
    {
        const int f0  = tid * 4;
        const int bl  = (f0 >> 2) & 3;
        const int byR = f0 >> 10;          // = tid >> 8? no: f0>>4 gives g16; decode below
        const int g16 = f0 >> 4;           // by*16 + tx
        const int b   = b0 + (g16 >> 4) * 4 + bl;
        const int i0  = n0 + (g16 & 15) * 8;
        (void)byR;

        u64 r[4];
#pragma unroll
        for (int j = 0; j < 4; j++) {
            u64 s = part[f0 + j];
            s = fadd2(s, part[1024 + f0 + j]);
            s = fadd2(s, part[2048 + f0 + j]);
            s = fadd2(s, part[3072 + f0 + j]);
            r[j] = s;
        }
        const long rowoff = (long)b * 512 + i0;
        if (Mul) {
            const u64* mp = reinterpret_cast<const u64*>(Mul + (long)g * BB * 512 + rowoff);
#pragma unroll
            for (int j = 0; j < 4; j++) r[j] = fmul2(r[j], mp[j]);
        }
        if (Add) {
            const u64* ap = reinterpret_cast<const u64*>(Add + (long)g * addStrideG + rowoff);
#pragma unroll
            for (int j = 0; j < 4; j++) r[j] = fadd2(r[j], ap[j]);
        }
        u64* op = reinterpret_cast<u64*>(Out + (long)g * outStrideG + rowoff);
#pragma unroll
        for (int j = 0; j < 4; j++) op[j] = r[j];
    }
}

static void launch_rec(const float* A, const float* W, float* Out,
                       const float* Mul, const float* Add,
                       int K, long aStrideG, long outStrideG, long addStrideG)
{
    dim3 grid(4, 8, GG), block(256);
    rec_gemm<<<grid, block>>>(A, W, Out, Mul, Add, K, aStrideG, outStrideG, addStrideG);
}

// ============ generic tiled SGEMM (FFMA2, conflict-free LDS) ============
// outMode 0: C[g*M*N + m*N + n]; outMode 1: logits remap C[(b*TS+t)*N + n]
template<int BM, int BN, int BK, int TM, int TN, int TX, int TY>
__global__ void __launch_bounds__(TX * TY)
sgemm_k(const float* __restrict__ A, const float* __restrict__ W,
        float* __restrict__ C,
        const float* __restrict__ Mul,
        const float* __restrict__ Add,
        const float* __restrict__ Bias,
        int M, int N, int K,
        long aStrideG, long addStrideG, int addModB, int outMode)
{
    constexpr int BKP = BK + 2;
    static_assert(BK % 4 == 0 && BKP % 2 == 0, "");
    __shared__ __align__(16) float As[BM * BKP];
    __shared__ __align__(16) float Ws[BN * BKP];

    const int g  = blockIdx.z;
    const int m0 = blockIdx.y * BM;
    const int n0 = blockIdx.x * BN;
    const float* Ag = A + (long)g * aStrideG;
    const float* Wg = W + (long)g * (long)K * N;
    const int tx = threadIdx.x, ty = threadIdx.y;
    const int tid = ty * TX + tx;
    const int NT  = TX * TY;

    u64 acc[TM][TN];
#pragma unroll
    for (int i = 0; i < TM; i++)
#pragma unroll
        for (int j = 0; j < TN; j++) acc[i][j] = 0ull;

    const u64* As64 = reinterpret_cast<const u64*>(As);
    const u64* Ws64 = reinterpret_cast<const u64*>(Ws);

    for (int k0 = 0; k0 < K; k0 += BK) {
        for (int idx = tid; idx < BM * (BK / 4); idx += NT) {
            int mm = idx / (BK / 4), kq = idx % (BK / 4);
            int m = m0 + mm, k = k0 + kq * 4;
            float4 v;
            if (m < M && k + 3 < K) {
                v = *reinterpret_cast<const float4*>(Ag + (long)m * K + k);
            } else {
                v.x = (m < M && k + 0 < K) ? Ag[(long)m * K + k + 0] : 0.f;
                v.y = (m < M && k + 1 < K) ? Ag[(long)m * K + k + 1] : 0.f;
                v.z = (m < M && k + 2 < K) ? Ag[(long)m * K + k + 2] : 0.f;
                v.w = (m < M && k + 3 < K) ? Ag[(long)m * K + k + 3] : 0.f;
            }
            float* dst = As + mm * BKP + kq * 4;
            dst[0] = v.x; dst[1] = v.y; dst[2] = v.z; dst[3] = v.w;
        }
        for (int idx = tid; idx < BK * (BN / 4); idx += NT) {
            int kk = idx / (BN / 4), nq = idx % (BN / 4);
            int k = k0 + kk, n = n0 + nq * 4;
            float4 v;
            if (k < K && n + 3 < N) {
                v = *reinterpret_cast<const float4*>(Wg + (long)k * N + n);
            } else {
                v.x = (k < K && n + 0 < N) ? Wg[(long)k * N + n + 0] : 0.f;
                v.y = (k < K && n + 1 < N) ? Wg[(long)k * N + n + 1] : 0.f;
                v.z = (k < K && n + 2 < N) ? Wg[(long)k * N + n + 2] : 0.f;
                v.w = (k < K && n + 3 < N) ? Wg[(long)k * N + n + 3] : 0.f;
            }
            Ws[(nq * 4 + 0) * BKP + kk] = v.x;
            Ws[(nq * 4 + 1) * BKP + kk] = v.y;
            Ws[(nq * 4 + 2) * BKP + kk] = v.z;
            Ws[(nq * 4 + 3) * BKP + kk] = v.w;
        }
        __syncthreads();

#pragma unroll
        for (int kp = 0; kp < BK / 2; kp++) {
            u64 a2[TM], b2[TN];
#pragma unroll
            for (int i = 0; i < TM; i++)
                a2[i] = As64[(ty + i * TY) * (BKP / 2) + kp];
#pragma unroll
            for (int j = 0; j < TN; j++)
                b2[j] = Ws64[(tx + j * TX) * (BKP / 2) + kp];
#pragma unroll
            for (int i = 0; i < TM; i++)
#pragma unroll
                for (int j = 0; j < TN; j++)
                    acc[i][j] = ffma2(a2[i], b2[j], acc[i][j]);
        }
        __syncthreads();
    }

#pragma unroll
    for (int i = 0; i < TM; i++) {
        int m = m0 + ty + i * TY;
        if (m >= M) continue;
        int bb = m % BB;
#pragma unroll
        for (int j = 0; j < TN; j++) {
            int n = n0 + tx + j * TX;
            if (n >= N) continue;
            float v = hadd2(acc[i][j]);
            if (Mul)  v *= Mul[(long)g * BB * N + (long)bb * N + n];
            if (Add)  v += Add[(long)g * addStrideG + (long)(addModB ? bb : m) * N + n];
            if (Bias) v += Bias[(long)g * N + n];
            long o = (outMode == 0) ? ((long)g * M * N + (long)m * N + n)
                                    : (((long)bb * TS + (m / BB)) * (long)N + n);
            C[o] = v;
        }
    }
}

// big GEMMs: 128x64 tile, TM=8 x TN=4 -> FMA-bound inner loop
static void launch_big(const float* A, const float* W, float* C,
                       const float* Mul, const float* Add, const float* Bias,
                       int M, int N, int K, int G,
                       long aStrideG, long addStrideG, int addModB, int outMode)
{
    dim3 grid((N + 63) / 64, (M + 127) / 128, G), block(16, 16);
    sgemm_k<128, 64, 16, 8, 4, 16, 16><<<grid, block>>>(
        A, W, C, Mul, Add, Bias, M, N, K, aStrideG, addStrideG, addModB, outMode);
}

// fallback 64x64 (used only for avbv: K=2048 exceeds rec_gemm smem)
static void launch_mid(const float* A, const float* W, float* C,
                       const float* Mul, const float* Add, const float* Bias,
                       int M, int N, int K, int G,
                       long aStrideG, long addStrideG, int addModB, int outMode)
{
    dim3 grid((N + 63) / 64, (M + 63) / 64, G), block(16, 16);
    sgemm_k<64, 64, 16, 4, 4, 16, 16><<<grid, block>>>(
        A, W, C, Mul, Add, Bias, M, N, K, aStrideG, addStrideG, addModB, outMode);
}

// ---------------- small helper kernels ----------------
__global__ void k_zero2(float* a, float* b, int n)
{
    int i = blockIdx.x * blockDim.x + threadIdx.x;
    if (i < n) { a[i] = 0.f; b[i] = 0.f; }
}

__global__ void k_embed(const int* __restrict__ cap, const float* __restrict__ table,
                        float* __restrict__ embs)
{
    int tb = blockIdx.x;              // 0 .. TS*B-1
    int t = tb / BB, b = tb % BB;
    int tok = cap[b * TT + t];
    const float4* src = reinterpret_cast<const float4*>(table + (long)tok * EE);
    float4* dst = reinterpret_cast<float4*>(embs + (long)tb * EE);
    dst[threadIdx.x] = src[threadIdx.x];
}

__global__ void k_update(const float* __restrict__ gates, float* __restrict__ c,
                         float* __restrict__ h, float* __restrict__ hall_t)
{
    int idx = blockIdx.x * blockDim.x + threadIdx.x;
    if (idx >= BB * HH) return;
    float gi = gates[0 * BB * HH + idx];
    float gf = gates[1 * BB * HH + idx];
    float go = gates[2 * BB * HH + idx];
    float gg = gates[3 * BB * HH + idx];
    float i_g = 1.f / (1.f + expf(-gi));
    float f_g = 1.f / (1.f + expf(-gf));
    float o_g = 1.f / (1.f + expf(-go));
    float g_g = tanhf(gg);
    float cc = f_g * c[idx] + i_g * g_g;
    float hh = o_g * tanhf(cc);
    c[idx] = cc;
    h[idx] = hh;
    hall_t[idx] = hh;
}

// ---------------- launch ----------------
extern "C" void kernel_launch(void* const* d_in, const int* in_sizes, int n_in,
                              void* d_out, int out_size)
{
    const int*   cap   = (const int*)  d_in[0];
    const float* cnn   = (const float*)d_in[1];
    const float* sem   = (const float*)d_in[2];
    const float* Wa_x  = (const float*)d_in[3];
    const float* Wb_x  = (const float*)d_in[4];
    const float* Wc_x  = (const float*)d_in[5];
    const float* Wa_h  = (const float*)d_in[6];
    const float* Wb_h  = (const float*)d_in[7];
    const float* Wc_h  = (const float*)d_in[8];
    const float* Wa_v  = (const float*)d_in[9];
    const float* Wb_v  = (const float*)d_in[10];
    const float* Wc_v  = (const float*)d_in[11];
    const float* bias  = (const float*)d_in[12];
    const float* table = (const float*)d_in[13];
    const float* Wout  = (const float*)d_in[14];
    const float* bout  = (const float*)d_in[15];
    float* out = (float*)d_out;

    float* S = nullptr;
    cudaGetSymbolAddress((void**)&S, g_scratch);
    float* bx    = S + OFF_BX;
    float* bh    = S + OFF_BH;
    float* bv    = S + OFF_BV;
    float* avbv  = S + OFF_AV;
    float* cv    = S + OFF_CV;
    float* embs  = S + OFF_EMBS;
    float* axb   = S + OFF_AXB;
    float* pre   = S + OFF_PRE;
    float* ahb   = S + OFF_AHB;
    float* gates = S + OFF_GATES;
    float* h     = S + OFF_H;
    float* c     = S + OFF_C;
    float* hall  = S + OFF_HALL;

    const long BN512 = (long)BB * 512;

    // reset recurrent state (deterministic per call)
    k_zero2<<<(BB * HH + 255) / 256, 256>>>(h, c, BB * HH);

    // embedding gather (time-major)
    k_embed<<<TS * BB, 128>>>(cap, table, embs);

    // semantics projections: bx/bh/bv[g,b,i] = sem @ Wb_*  (K=300)
    launch_rec(sem, Wb_x, bx, nullptr, nullptr, SS, 0, BN512, 0);
    launch_rec(sem, Wb_h, bh, nullptr, nullptr, SS, 0, BN512, 0);
    launch_rec(sem, Wb_v, bv, nullptr, nullptr, SS, 0, BN512, 0);

    // av*bv fused: (cnn @ Wa_v) * bv   (K=2048 -> generic path)
    launch_mid(cnn, Wa_v, avbv, bv, nullptr, nullptr, BB, II, CC, GG, 0, 0, 0, 0);
    // cv[g,b,h] = (av*bv) @ Wc_v
    launch_rec(avbv, Wc_v, cv, nullptr, nullptr, II, BN512, BN512, 0);

    // All-timestep input path: axb[g,(t,b),i] = (embs @ Wa_x) * bx
    launch_big(embs, Wa_x, axb, bx, nullptr, nullptr, TS * BB, II, EE, GG, 0, 0, 0, 0);
    // pre[g,(t,b),h] = axb @ Wc_x + cv + bias
    launch_big(axb, Wc_x, pre, nullptr, cv, bias, TS * BB, HH, II, GG,
               (long)TS * BB * II, (long)BB * HH, 1, 0);

    // Sequential recurrence
    for (int t = 0; t < TS; t++) {
        // ahb[g,b,i] = (h @ Wa_h) * bh
        launch_rec(h, Wa_h, ahb, bh, nullptr, HH, 0, BN512, 0);
        // gates[g,b,j] = ahb @ Wc_h + pre[g,t,b,j]
        launch_rec(ahb, Wc_h, gates, nullptr, pre + (long)t * BB * HH,
                   II, BN512, BN512, (long)TS * BB * HH);
        // LSTM cell update; store h into hall[t]
        k_update<<<(BB * HH + 255) / 256, 256>>>(gates, c, h, hall + (long)t * BB * HH);
    }

    // Logits: out[b,t,v] = hall[(t,b),:] @ Wout + bout
    launch_big(hall, Wout, out, nullptr, nullptr, bout, TS * BB, VV, HH, 1, 0, 0, 0, 1);
}